// round 10
// baseline (speedup 1.0000x reference)
#include <cuda_runtime.h>

#define NAGENTS 8192
#define OBSLEN  20
#define PREDLEN 30
#define EMBED   64
#define HIDDEN  128
#define CNNOUT  2048
#define GATES   512   /* 4*HIDDEN */
#define KDIM    192   /* EMBED + HIDDEN */

// Weight layout (unit-paired): ull g_Wd[((k*2+h)*32+lane)*4+e] =
//   ( W[j_lo][k], W[j_hi][k] ),  j_lo = e*128 + h*64 + lane, j_hi = j_lo + 32.
// Lane reads 32B/k (2x LDG.128). Extra zero k-row pads the prefetch.
// Per-k stride = 256 ull = 128 ulonglong2.
__device__ unsigned long long g_Wd[(KDIM + 1) * 2 * 32 * 4];
__device__ float g_bias[GATES];
__device__ float g_imgproj[NAGENTS * 2];

// ---------------------------------------------------------------------------
// Combined prep: blocks [0,1024) img projection; [1024,1408) weights+bias.
// ---------------------------------------------------------------------------
__global__ void prep_all(const float* __restrict__ img,
                         const float* __restrict__ pred_W,
                         const float* __restrict__ W_ih,
                         const float* __restrict__ W_hh,
                         const float* __restrict__ b_ih,
                         const float* __restrict__ b_hh) {
    int bid = blockIdx.x;
    if (bid < 1024) {
        int warp = threadIdx.x >> 5, lane = threadIdx.x & 31;
        int n = bid * 8 + warp;
        const float4* ip = (const float4*)(img + (size_t)n * CNNOUT);
        const float4* w0 = (const float4*)(pred_W + HIDDEN);
        const float4* w1 = (const float4*)(pred_W + (HIDDEN + CNNOUT) + HIDDEN);
        float s0 = 0.f, s1 = 0.f;
        for (int i = lane; i < CNNOUT / 4; i += 32) {
            float4 v = ip[i], a = w0[i], b = w1[i];
            s0 += v.x * a.x + v.y * a.y + v.z * a.z + v.w * a.w;
            s1 += v.x * b.x + v.y * b.y + v.z * b.z + v.w * b.w;
        }
#pragma unroll
        for (int o = 16; o; o >>= 1) {
            s0 += __shfl_xor_sync(0xFFFFFFFFu, s0, o);
            s1 += __shfl_xor_sync(0xFFFFFFFFu, s1, o);
        }
        if (lane == 0) { g_imgproj[n * 2] = s0; g_imgproj[n * 2 + 1] = s1; }
    } else {
        int idx = (bid - 1024) * 256 + threadIdx.x;
        if (idx < KDIM * GATES) {
            int k = idx / GATES, j = idx % GATES;
            int e = j >> 7, r = j & 127;
            int h = r >> 6, l6 = r & 63;
            int lane = l6 & 31, hi = l6 >> 5;
            float v = (k < EMBED) ? W_ih[j * EMBED + k] : W_hh[j * HIDDEN + (k - EMBED)];
            ((float*)g_Wd)[((((k * 2 + h) * 32 + lane) * 4 + e) << 1) + hi] = v;
        }
        if (idx < GATES) g_bias[idx] = b_ih[idx] + b_hh[idx];
    }
}

__device__ __forceinline__ float sigf(float x) {
    return __fdividef(1.f, 1.f + __expf(-x));
}
__device__ __forceinline__ float tanhfast(float x) {
    float e = __expf(-2.f * fabsf(x));
    float r = __fdividef(1.f - e, 1.f + e);
    return copysignf(r, x);
}

__device__ __forceinline__ unsigned long long pack2(float lo, float hi) {
    unsigned long long r;
    asm("mov.b64 %0, {%1, %2};" : "=l"(r) : "f"(lo), "f"(hi));
    return r;
}
__device__ __forceinline__ float2 unpk(unsigned long long v) {
    float2 r;
    asm("mov.b64 {%0, %1}, %2;" : "=f"(r.x), "=f"(r.y) : "l"(v));
    return r;
}
#define FF2(a, w, i) asm("fma.rn.f32x2 %0, %1, %2, %0;" : "+l"(a) : "l"(w), "l"(i))
#define BARW(id) asm volatile("bar.sync %0, 64;" :: "r"(id) : "memory")

#define IN_DUP_ULL (4 * KDIM * 8)
#define SMEM_FLOATS (IN_DUP_ULL * 2 + 512 + 192 + 256 + 192 + 32)
#define SMEM_BYTES (SMEM_FLOATS * 4)

// ---------------------------------------------------------------------------
// 256 threads = 4 warp-pairs; 8 agents per pair. Warp (2g+h) owns units
// h*64+lane (m=0) and h*64+32+lane (m=1). f32x2 pairs UNITS; weights come
// prepacked from gmem (no MOVs); inputs pre-duplicated (v,v) in smem.
// ---------------------------------------------------------------------------
__global__ __launch_bounds__(256, 2) void lstm_main(
    const float* __restrict__ obs_pos, const int* __restrict__ hist,
    const float* __restrict__ obs_rel, const float* __restrict__ h0,
    const float* __restrict__ embed_W, const float* __restrict__ embed_b,
    const float* __restrict__ pred_W,  const float* __restrict__ pred_b,
    float* __restrict__ out) {
    extern __shared__ unsigned long long smu[];
    unsigned long long (*in_dup)[KDIM][8] = (unsigned long long(*)[KDIM][8])smu; // [g][k][a]=(v,v)
    unsigned long long (*b2_s)[32][4] = (unsigned long long(*)[32][4])(smu + IN_DUP_ULL); // [h][lane][e]
    float* fb = (float*)(smu + IN_DUP_ULL + 256);
    float* ew0 = fb;            // 64
    float* ew1 = ew0 + 64;
    float* eb  = ew1 + 64;
    float* pw  = eb + 64;       // [2][128]
    float (*src_s)[8][2]  = (float(*)[8][2])(pw + 256);
    float (*pos_s)[8][2]  = (float(*)[8][2])(pw + 256 + 64);
    float (*imgp_s)[8][2] = (float(*)[8][2])(pw + 256 + 128);
    int*   hist_s         = (int*)(pw + 256 + 192);

    int tid = threadIdx.x, warp = tid >> 5, lane = tid & 31;
    int g = warp >> 1, half = warp & 1;
    int ab = blockIdx.x * 32;
    int a0 = g * 8;
    int barid = g + 1;

    // ---------------- init ----------------
    for (int i = tid; i < GATES; i += 256) {
        int h = i >> 7, lane_i = (i >> 2) & 31, e = i & 3;
        int jlo = e * 128 + h * 64 + lane_i;
        b2_s[h][lane_i][e] = pack2(g_bias[jlo], g_bias[jlo + 32]);
    }
    if (tid < EMBED) {
        ew0[tid] = embed_W[tid * 2];
        ew1[tid] = embed_W[tid * 2 + 1];
        eb[tid]  = embed_b[tid];
    }
    for (int i = tid; i < 2 * HIDDEN; i += 256)
        pw[i] = pred_W[(i >> 7) * (HIDDEN + CNNOUT) + (i & 127)];
    if (tid < 32) hist_s[tid] = hist[ab + tid];
    if (tid < 64) {
        int a = tid >> 1, d = tid & 1;
        pos_s[a >> 3][a & 7][d]  = obs_pos[(size_t)(ab + a) * OBSLEN * 2 + (OBSLEN - 1) * 2 + d];
        imgp_s[a >> 3][a & 7][d] = g_imgproj[(ab + a) * 2 + d];
    }
    for (int i = tid; i < 4 * KDIM * 8; i += 256) {
        int k = (i >> 3) % KDIM;
        float v = (k < EMBED) ? 0.f : h0[k - EMBED];
        ((unsigned long long*)in_dup)[i] = pack2(v, v);
    }
    float c[2][8];
#pragma unroll
    for (int m = 0; m < 2; m++) {
        float hv = h0[half * 64 + lane + 32 * m];
#pragma unroll
        for (int a = 0; a < 8; a++) c[m][a] = hv;
    }
    float pbd = pred_b[(lane >> 2) & 1];
    __syncthreads();

    int maxh8 = hist_s[a0];
#pragma unroll
    for (int a = 1; a < 8; a++) maxh8 = max(maxh8, hist_s[a0 + a]);

    // ---------------- 49 sequential steps ----------------
    for (int step = 0; step < OBSLEN - 1 + PREDLEN; step++) {
        bool obsPhase = step < OBSLEN - 1;
        int t = obsPhase ? (step + 1) : (step - (OBSLEN - 1));

        if (obsPhase) {
            if (maxh8 <= OBSLEN - t) continue;
            if (half == 0 && lane < 16) {
                int a = lane >> 1, d = lane & 1;
                src_s[g][a][d] = obs_rel[(size_t)(ab + a0 + a) * OBSLEN * 2 + t * 2 + d];
            }
            BARW(barid);
        } else {
            // disp = h @ pred_W[:, :128].T + img_proj + pred_b
            int task = lane >> 2, sub = lane & 3;
            int a = half * 4 + (task >> 1), d = task & 1;
            const float* inf = (const float*)in_dup[g];
            float s = 0.f;
#pragma unroll 8
            for (int kk = 0; kk < 32; kk++) {
                int k = sub * 32 + kk;
                s = fmaf(pw[d * 128 + k], inf[((EMBED + k) * 8 + a) * 2], s);
            }
            s += __shfl_xor_sync(0xFFFFFFFFu, s, 1);
            s += __shfl_xor_sync(0xFFFFFFFFu, s, 2);
            if (sub == 0) {
                s += imgp_s[g][a][d] + pbd;
                float p = pos_s[g][a][d] + s;
                pos_s[g][a][d] = p;
                out[(size_t)(ab + a0 + a) * PREDLEN * 2 + t * 2 + d] = p;
                src_s[g][a][d] = s;
            }
            BARW(barid);
        }

        // embed -> duplicated input rows (warp h writes rows h*32..h*32+31)
        {
            int k = half * 32 + lane;
            float w0 = ew0[k], w1 = ew1[k], bb = eb[k];
#pragma unroll
            for (int a = 0; a < 8; a++) {
                float x = fmaxf(fmaf(w0, src_s[g][a][0], fmaf(w1, src_s[g][a][1], bb)), 0.f);
                in_dup[g][k][a] = pack2(x, x);
            }
        }
        BARW(barid);

        // ---- gate GEMM: acc[e][a] = f32x2 over unit pair (lane, lane+32) ----
        unsigned long long acc[4][8];
#pragma unroll
        for (int e = 0; e < 4; e++) {
            unsigned long long b = b2_s[half][lane][e];
#pragma unroll
            for (int a = 0; a < 8; a++) acc[e][a] = b;
        }
        const ulonglong2* wp = (const ulonglong2*)(g_Wd + ((0 * 2 + half) * 32 + lane) * 4);
        const ulonglong2* inp = (const ulonglong2*)in_dup[g];
        ulonglong2 w01 = wp[0], w23 = wp[1];
#pragma unroll 2
        for (int k = 0; k < KDIM; k++) {
            const ulonglong2* np = wp + 128;     // per-k stride = 256 ull = 128 ull2 (FIXED)
            ulonglong2 n01 = np[0], n23 = np[1];
            ulonglong2 iA = inp[4 * k], iB = inp[4 * k + 1];
            FF2(acc[0][0], w01.x, iA.x); FF2(acc[1][0], w01.y, iA.x);
            FF2(acc[2][0], w23.x, iA.x); FF2(acc[3][0], w23.y, iA.x);
            FF2(acc[0][1], w01.x, iA.y); FF2(acc[1][1], w01.y, iA.y);
            FF2(acc[2][1], w23.x, iA.y); FF2(acc[3][1], w23.y, iA.y);
            FF2(acc[0][2], w01.x, iB.x); FF2(acc[1][2], w01.y, iB.x);
            FF2(acc[2][2], w23.x, iB.x); FF2(acc[3][2], w23.y, iB.x);
            FF2(acc[0][3], w01.x, iB.y); FF2(acc[1][3], w01.y, iB.y);
            FF2(acc[2][3], w23.x, iB.y); FF2(acc[3][3], w23.y, iB.y);
            ulonglong2 iC = inp[4 * k + 2], iD = inp[4 * k + 3];
            FF2(acc[0][4], w01.x, iC.x); FF2(acc[1][4], w01.y, iC.x);
            FF2(acc[2][4], w23.x, iC.x); FF2(acc[3][4], w23.y, iC.x);
            FF2(acc[0][5], w01.x, iC.y); FF2(acc[1][5], w01.y, iC.y);
            FF2(acc[2][5], w23.x, iC.y); FF2(acc[3][5], w23.y, iC.y);
            FF2(acc[0][6], w01.x, iD.x); FF2(acc[1][6], w01.y, iD.x);
            FF2(acc[2][6], w23.x, iD.x); FF2(acc[3][6], w23.y, iD.x);
            FF2(acc[0][7], w01.x, iD.y); FF2(acc[1][7], w01.y, iD.y);
            FF2(acc[2][7], w23.x, iD.y); FF2(acc[3][7], w23.y, iD.y);
            w01 = n01; w23 = n23; wp = np;
        }

        // ---- cell update; h written back duplicated ----
        bool upd[8];
#pragma unroll
        for (int a = 0; a < 8; a++)
            upd[a] = !obsPhase || (hist_s[a0 + a] > OBSLEN - t);
        float h2[2][8];
#pragma unroll
        for (int a = 0; a < 8; a++) {
            float2 I = unpk(acc[0][a]);
            float2 F = unpk(acc[1][a]);
            float2 G = unpk(acc[2][a]);
            float2 O = unpk(acc[3][a]);
            if (upd[a]) {
                float c20 = sigf(F.x) * c[0][a] + sigf(I.x) * tanhfast(G.x);
                float c21 = sigf(F.y) * c[1][a] + sigf(I.y) * tanhfast(G.y);
                c[0][a] = c20; c[1][a] = c21;
                h2[0][a] = sigf(O.x) * tanhfast(c20);
                h2[1][a] = sigf(O.y) * tanhfast(c21);
            } else {
                h2[0][a] = unpk(in_dup[g][EMBED + half * 64 + lane][a]).x;
                h2[1][a] = unpk(in_dup[g][EMBED + half * 64 + 32 + lane][a]).x;
            }
        }
#pragma unroll
        for (int m = 0; m < 2; m++) {
            int row = EMBED + half * 64 + 32 * m + lane;
#pragma unroll
            for (int a = 0; a < 8; a++)
                in_dup[g][row][a] = pack2(h2[m][a], h2[m][a]);
        }
        BARW(barid);   // h visible to partner warp
    }
}

extern "C" void kernel_launch(void* const* d_in, const int* in_sizes, int n_in,
                              void* d_out, int out_size) {
    const float* img     = (const float*)d_in[0];
    const float* obs_pos = (const float*)d_in[1];
    const int*   hist    = (const int*)d_in[2];
    const float* obs_rel = (const float*)d_in[3];
    const float* h0      = (const float*)d_in[4];
    const float* W_ih    = (const float*)d_in[5];
    const float* W_hh    = (const float*)d_in[6];
    const float* b_ih    = (const float*)d_in[7];
    const float* b_hh    = (const float*)d_in[8];
    const float* embed_W = (const float*)d_in[9];
    const float* embed_b = (const float*)d_in[10];
    const float* pred_W  = (const float*)d_in[11];
    const float* pred_b  = (const float*)d_in[12];
    float* out = (float*)d_out;

    cudaFuncSetAttribute(lstm_main, cudaFuncAttributeMaxDynamicSharedMemorySize, SMEM_BYTES);
    prep_all<<<1024 + 384, 256>>>(img, pred_W, W_ih, W_hh, b_ih, b_hh);
    lstm_main<<<NAGENTS / 32, 256, SMEM_BYTES>>>(obs_pos, hist, obs_rel, h0,
                                                 embed_W, embed_b, pred_W, pred_b, out);
}